// round 15
// baseline (speedup 1.0000x reference)
#include <cuda_runtime.h>
#include <cstdint>

// PSRoIAlign: feat [B=4, C=784, H=80, W=80] fp32, rois [512,5] fp32
// out [512, 16, 7, 7] fp32.
//
// R15: plane-stationary + pipelining.  R11 was right to kill the divergent-
// LDG wavefront floor, but serialized copy->compute per tiny CTA.  Now each
// CTA owns 8 consecutive planes with a double-buffered cp.async.bulk ring:
// copy of plane s+1 overlaps compute of plane s.  Streaming floor:
// 80MB @ ~6300 B/cyc LTS ~= 7.3us; compute and scattered STG hide under it.

#define B_    4
#define CO_   16
#define PH_   7
#define PW_   7
#define H_    80
#define W_    80
#define C_    (CO_ * PH_ * PW_)     // 784
#define HW_   (H_ * W_)             // 6400
#define NROI  512
#define NPLANE (B_ * C_)            // 3136
#define PLANE_BYTES (HW_ * 4)       // 25600
#define PPB   8                     // planes per block
#define GRID  (NPLANE / PPB)        // 392
#define TPB   128
#define SMEM_DYN (2 * PLANE_BYTES)  // 51200

__device__ float4 g_params[B_ * NROI];  // compacted {x1,y1,x2,y2} per batch
__device__ int    g_nidx[B_ * NROI];    // compacted roi index
__device__ int    g_cnt[B_];

// ---------------- K1: bucket ROIs by batch ----------------
__global__ void bucket_rois_kernel(const float* __restrict__ rois)
{
    __shared__ int scnt[B_];
    const int t = threadIdx.x;
    if (t < B_) scnt[t] = 0;
    __syncthreads();
    if (t < NROI) {
        const float* r = rois + t * 5;
        const int b = (int)r[0];
        float4 p = make_float4(r[1], r[2], r[3], r[4]);
        int pos = atomicAdd(&scnt[b], 1);
        g_params[b * NROI + pos] = p;
        g_nidx[b * NROI + pos]   = t;
    }
    __syncthreads();
    if (t < B_) g_cnt[t] = scnt[t];
}

// ---------------- mbarrier helpers ----------------
__device__ __forceinline__ void mbar_init(uint32_t mb, uint32_t cnt) {
    asm volatile("mbarrier.init.shared.b64 [%0], %1;" :: "r"(mb), "r"(cnt));
}
__device__ __forceinline__ void mbar_expect_tx(uint32_t mb, uint32_t bytes) {
    asm volatile("mbarrier.arrive.expect_tx.shared.b64 _, [%0], %1;"
                 :: "r"(mb), "r"(bytes));
}
__device__ __forceinline__ void bulk_copy(uint32_t dst, const float* src,
                                          uint32_t bytes, uint32_t mb) {
    asm volatile(
        "cp.async.bulk.shared::cta.global.mbarrier::complete_tx::bytes "
        "[%0], [%1], %2, [%3];"
        :: "r"(dst), "l"(src), "r"(bytes), "r"(mb) : "memory");
}
__device__ __forceinline__ void mbar_wait(uint32_t mb, uint32_t phase) {
    uint32_t done;
    asm volatile(
        "{\n\t.reg .pred p;\n\t"
        "mbarrier.try_wait.parity.acquire.cta.shared::cta.b64 p, [%1], %2;\n\t"
        "selp.b32 %0, 1, 0, p;\n\t}"
        : "=r"(done) : "r"(mb), "r"(phase) : "memory");
    while (!done) {
        asm volatile(
            "{\n\t.reg .pred p;\n\t"
            "mbarrier.try_wait.parity.acquire.cta.shared::cta.b64 p, [%1], %2, 0x989680;\n\t"
            "selp.b32 %0, 1, 0, p;\n\t}"
            : "=r"(done) : "r"(mb), "r"(phase) : "memory");
    }
}

// ---------------- K2: pipelined plane-stationary PSRoIAlign ----------------
__global__ __launch_bounds__(TPB)
void psroi_plane_kernel(const float* __restrict__ feat,
                        float* __restrict__ out)
{
    extern __shared__ __align__(128) float buf[];      // [2][HW_]
    __shared__ __align__(8) uint64_t mbar[2];

    const int p0  = blockIdx.x * PPB;                  // first plane
    const int tid = threadIdx.x;

    const uint32_t mb0 = (uint32_t)__cvta_generic_to_shared(&mbar[0]);
    const uint32_t mb1 = (uint32_t)__cvta_generic_to_shared(&mbar[1]);
    const uint32_t d0  = (uint32_t)__cvta_generic_to_shared(buf);
    const uint32_t d1  = d0 + PLANE_BYTES;

    if (tid == 0) { mbar_init(mb0, 1); mbar_init(mb1, 1); }
    __syncthreads();

    if (tid == 0) {
        mbar_expect_tx(mb0, PLANE_BYTES);
        bulk_copy(d0, feat + (size_t)p0 * HW_, PLANE_BYTES, mb0);
        mbar_expect_tx(mb1, PLANE_BYTES);
        bulk_copy(d1, feat + (size_t)(p0 + 1) * HW_, PLANE_BYTES, mb1);
    }

    int phase0 = 0, phase1 = 0;

    #pragma unroll 1
    for (int s = 0; s < PPB; s++) {
        const int pidx = p0 + s;
        const int b    = pidx / C_;
        const int c    = pidx - b * C_;
        const int bin  = c % (PH_ * PW_);
        const int j    = bin % PW_;
        const int i    = bin / PW_;
        const int st   = s & 1;

        // wait for this stage's copy
        if (st == 0) { mbar_wait(mb0, phase0); phase0 ^= 1; }
        else         { mbar_wait(mb1, phase1); phase1 ^= 1; }
        const float* plane = buf + st * HW_;

        const int len = g_cnt[b];
        for (int k = tid; k < len; k += TPB) {
            const float4 p = __ldg(&g_params[b * NROI + k]);
            const int    n = __ldg(&g_nidx[b * NROI + k]);

            const float x1 = p.x * (float)W_;
            const float y1 = p.y * (float)H_;
            const float x2 = p.z * (float)W_;
            const float y2 = p.w * (float)H_;

            const float bin_h = fmaxf(y2 - y1, 0.1f) * (1.0f / (float)PH_);
            const float bin_w = fmaxf(x2 - x1, 0.1f) * (1.0f / (float)PW_);

            int   y0i[2], y1i[2], x0i[2], x1i[2];
            float hy[2], ly[2], hx[2], lx[2];

            #pragma unroll
            for (int sq = 0; sq < 2; sq++) {
                float ys = y1 + (float)i * bin_h + ((float)sq + 0.5f) * bin_h * 0.5f;
                bool ym = (ys >= -1.0f) && (ys <= (float)H_);
                float yc = fminf(fmaxf(ys, 0.0f), (float)(H_ - 1));
                float yf = floorf(yc);
                y0i[sq] = (int)yf;
                y1i[sq] = min(y0i[sq] + 1, H_ - 1);
                ly[sq]  = ym ? (yc - yf) : 0.0f;
                hy[sq]  = ym ? (1.0f - (yc - yf)) : 0.0f;

                float xs = x1 + (float)j * bin_w + ((float)sq + 0.5f) * bin_w * 0.5f;
                bool xm = (xs >= -1.0f) && (xs <= (float)W_);
                float xc = fminf(fmaxf(xs, 0.0f), (float)(W_ - 1));
                float xf = floorf(xc);
                x0i[sq] = (int)xf;
                x1i[sq] = min(x0i[sq] + 1, W_ - 1);
                lx[sq]  = xm ? (xc - xf) : 0.0f;
                hx[sq]  = xm ? (1.0f - (xc - xf)) : 0.0f;
            }

            float sum = 0.0f;
            #pragma unroll
            for (int sy = 0; sy < 2; sy++) {
                const int r0 = y0i[sy] * W_;
                const int r1 = y1i[sy] * W_;
                #pragma unroll
                for (int sx = 0; sx < 2; sx++) {
                    const float v00 = plane[r0 + x0i[sx]];
                    const float v01 = plane[r0 + x1i[sx]];
                    const float v10 = plane[r1 + x0i[sx]];
                    const float v11 = plane[r1 + x1i[sx]];
                    sum += hy[sy] * (hx[sx] * v00 + lx[sx] * v01)
                         + ly[sy] * (hx[sx] * v10 + lx[sx] * v11);
                }
            }

            out[(size_t)n * C_ + c] = sum * 0.25f;
        }

        // all threads done reading buf[st] -> refill it with plane s+2
        __syncthreads();
        if (tid == 0 && s + 2 < PPB) {
            const uint32_t db = st ? d1 : d0;
            const uint32_t mb = st ? mb1 : mb0;
            mbar_expect_tx(mb, PLANE_BYTES);
            bulk_copy(db, feat + (size_t)(pidx + 2) * HW_, PLANE_BYTES, mb);
        }
    }
}

extern "C" void kernel_launch(void* const* d_in, const int* in_sizes, int n_in,
                              void* d_out, int out_size)
{
    const float* feat = (const float*)d_in[0];
    const float* rois = (const float*)d_in[1];
    float* out        = (float*)d_out;

    static int attr_set = 0;
    if (!attr_set) {
        cudaFuncSetAttribute(psroi_plane_kernel,
                             cudaFuncAttributeMaxDynamicSharedMemorySize,
                             SMEM_DYN);
        attr_set = 1;
    }

    bucket_rois_kernel<<<1, NROI>>>(rois);
    psroi_plane_kernel<<<GRID, TPB, SMEM_DYN>>>(feat, out);
}